// round 17
// baseline (speedup 1.0000x reference)
#include <cuda_runtime.h>
#include <cstdint>

#define N_NODES 16384
#define IN_F    256
#define OUT_F   64
#define KSPLIT  8
#define KRANGE  (N_NODES / KSPLIT)   // 2048
#define MBLOCKS (N_NODES / 128)      // 128
#define NTILES  (MBLOCKS * KSPLIT)   // 1024
#define PERSIST_CTAS 296             // 2 per SM x 148 SMs

// h = x@W + b, pre-rounded to tf32 bit pattern: [16384][64] f32 = 4MB
__device__ float g_h[N_NODES * OUT_F];
// split-K partials: [KSPLIT][16384][64] f32 = 32MB
__device__ float g_part[KSPLIT * N_NODES * OUT_F];
// work-stealing counter (reset each launch by reset_kernel)
__device__ int g_tile_ctr;

__device__ __forceinline__ uint32_t f2tf32(float f) {
    uint32_t u;
    asm("cvt.rna.tf32.f32 %0, %1;" : "=r"(u) : "f"(f));
    return u;
}
__device__ __forceinline__ void cp_async16(void* sm, const void* gm) {
    uint32_t s = (uint32_t)__cvta_generic_to_shared(sm);
    asm volatile("cp.async.cg.shared.global [%0], [%1], 16;" :: "r"(s), "l"(gm));
}

#define MMA_TF32(d, a, bf)                                                    \
    asm volatile(                                                             \
        "mma.sync.aligned.m16n8k8.row.col.f32.tf32.tf32.f32 "                 \
        "{%0,%1,%2,%3}, {%4,%5,%6,%7}, {%8,%9}, {%0,%1,%2,%3};"               \
        : "+f"(d[0]), "+f"(d[1]), "+f"(d[2]), "+f"(d[3])                      \
        : "r"(a[0]), "r"(a[1]), "r"(a[2]), "r"(a[3]), "r"(bf[0]), "r"(bf[1]))

// ---------------------------------------------------------------------------
// Kernel A: g_h = rna(x @ W + b)  via tf32 mma.sync (rna on both operands)
// BM=64 (grid 256), 256 thr = 8 warps: 2M x 2N x 2K-half; BK=32, NK=8
// ---------------------------------------------------------------------------
#define L_STAGES 4
#define L_A_F4   512
#define L_H_F4   512
#define L_ST_F4  (L_A_F4 + L_H_F4)
#define L_SMEM   (L_STAGES * L_ST_F4 * 16)   // 65536

__global__ __launch_bounds__(256) void linear_kernel(
    const float* __restrict__ x, const float* __restrict__ W,
    const float* __restrict__ b)
{
    extern __shared__ float4 smem[];

    const int tid  = threadIdx.x;
    const int lane = tid & 31;
    const int wid  = tid >> 5;
    const int wm   = wid & 1;
    const int wn   = (wid >> 1) & 1;
    const int kh   = wid >> 2;
    const int g    = lane >> 2;
    const int tig  = lane & 3;

    const size_t rowBase = (size_t)blockIdx.x * 64;
    const float* gA0 = x + rowBase * IN_F;

    float acc[2][4][4];
#pragma unroll
    for (int mt = 0; mt < 2; ++mt)
#pragma unroll
        for (int nt = 0; nt < 4; ++nt)
#pragma unroll
            for (int e = 0; e < 4; ++e) acc[mt][nt][e] = 0.f;

    const int NK = IN_F / 32;       // 8

    auto issue = [&](int kt) {
        const int st = kt & (L_STAGES - 1);
        float4* As4 = smem + st * L_ST_F4;
        float4* Hs4 = As4 + L_A_F4;
        const float* gA = gA0 + kt * 32;
#pragma unroll
        for (int i = 0; i < 2; ++i) {
            int e   = i * 256 + tid;
            int row = e >> 3;
            int c4  = e & 7;
            cp_async16(&As4[row * 8 + (c4 ^ (row & 7))],
                       gA + (size_t)row * IN_F + c4 * 4);
        }
        const float* gW = W + (size_t)kt * 32 * OUT_F;
#pragma unroll
        for (int i = 0; i < 2; ++i) {
            int e  = i * 256 + tid;
            int k  = e >> 4;
            int c4 = e & 15;
            cp_async16(&Hs4[k * 16 + (c4 ^ ((k & 3) << 1))],
                       gW + k * OUT_F + c4 * 4);
        }
    };

    issue(0); asm volatile("cp.async.commit_group;");
    issue(1); asm volatile("cp.async.commit_group;");
    issue(2); asm volatile("cp.async.commit_group;");

    for (int kt = 0; kt < NK; ++kt) {
        asm volatile("cp.async.wait_group 2;");
        __syncthreads();
        if (kt + 3 < NK) issue(kt + 3);
        asm volatile("cp.async.commit_group;");

        const int st = kt & (L_STAGES - 1);
        const float* As = (const float*)(smem + st * L_ST_F4);
        const float* Hs = (const float*)(smem + st * L_ST_F4 + L_A_F4);

#pragma unroll
        for (int ks = 0; ks < 2; ++ks) {
            const int k0 = kh * 16 + ks * 8 + tig;
            const int k1 = k0 + 4;
            uint32_t afr[2][4];
#pragma unroll
            for (int mt = 0; mt < 2; ++mt) {
                int r = wm * 32 + mt * 16 + g;
                afr[mt][0] = f2tf32(As[r * 32       + (((k0 >> 2) ^ (r & 7)) << 2) + (k0 & 3)]);
                afr[mt][1] = f2tf32(As[(r + 8) * 32 + (((k0 >> 2) ^ (r & 7)) << 2) + (k0 & 3)]);
                afr[mt][2] = f2tf32(As[r * 32       + (((k1 >> 2) ^ (r & 7)) << 2) + (k1 & 3)]);
                afr[mt][3] = f2tf32(As[(r + 8) * 32 + (((k1 >> 2) ^ (r & 7)) << 2) + (k1 & 3)]);
            }
            uint32_t bfr[4][2];
#pragma unroll
            for (int nt = 0; nt < 4; ++nt) {
                int n = wn * 32 + nt * 8 + g;
                bfr[nt][0] = f2tf32(Hs[k0 * 64 + (n ^ ((k0 & 3) << 3))]);
                bfr[nt][1] = f2tf32(Hs[k1 * 64 + (n ^ ((k1 & 3) << 3))]);
            }
#pragma unroll
            for (int mt = 0; mt < 2; ++mt)
#pragma unroll
                for (int nt = 0; nt < 4; ++nt)
                    MMA_TF32(acc[mt][nt], afr[mt], bfr[nt]);
        }
    }

    __syncthreads();
    float4* red = smem;
    const int wq = wid & 3;
    if (kh == 1) {
#pragma unroll
        for (int mt = 0; mt < 2; ++mt)
#pragma unroll
            for (int nt = 0; nt < 4; ++nt)
                red[((wq * 2 + mt) * 4 + nt) * 32 + lane] =
                    make_float4(acc[mt][nt][0], acc[mt][nt][1],
                                acc[mt][nt][2], acc[mt][nt][3]);
    }
    __syncthreads();
    if (kh == 0) {
#pragma unroll
        for (int mt = 0; mt < 2; ++mt) {
            size_t r = rowBase + wm * 32 + mt * 16 + g;
#pragma unroll
            for (int nt = 0; nt < 4; ++nt) {
                float4 o = red[((wq * 2 + mt) * 4 + nt) * 32 + lane];
                int c = wn * 32 + nt * 8 + tig * 2;
                float b0 = b[c], b1 = b[c + 1];
                float2 v0, v1;
                v0.x = __uint_as_float(f2tf32(acc[mt][nt][0] + o.x + b0));
                v0.y = __uint_as_float(f2tf32(acc[mt][nt][1] + o.y + b1));
                v1.x = __uint_as_float(f2tf32(acc[mt][nt][2] + o.z + b0));
                v1.y = __uint_as_float(f2tf32(acc[mt][nt][3] + o.w + b1));
                *(float2*)&g_h[r * OUT_F + c]       = v0;
                *(float2*)&g_h[(r + 8) * OUT_F + c] = v1;
            }
        }
    }
}

// ---------------------------------------------------------------------------
// reset work-stealing counter (runs before agg each launch/replay)
// ---------------------------------------------------------------------------
__global__ void reset_kernel() { g_tile_ctr = 0; }

// ---------------------------------------------------------------------------
// Kernel B (persistent): tiles (mb, kz): g_part[kz][mb*128:+128] += adj@h
// BM=128, BN=64, BK=32; 296 CTAs (2/SM); 8 warps = 4M x 2N (32x32 tile)
// 4-stage cp.async pipeline, 96KB smem; work-stealing via g_tile_ctr
// tile id s: kz = s>>7, mb = s&127  (consecutive ids share the h slice)
// A: raw f32 bits (HW tf32 trunc); H pre-rounded rna
// ---------------------------------------------------------------------------
#define STAGES 4
#define BK     32
#define A_ST_F4 1024                // 128 x 32 f32 = 16KB
#define H_ST_F4 512                 // 32 x 64 f32 = 8KB
#define ST_F4   (A_ST_F4 + H_ST_F4)
#define SMEM_BYTES (STAGES * ST_F4 * 16)   // 98304

__global__ __launch_bounds__(256, 2) void agg_kernel(
    const float* __restrict__ adj)
{
    extern __shared__ float4 smem[];
    __shared__ int s_tile;

    const int tid   = threadIdx.x;
    const int lane  = tid & 31;
    const int wid   = tid >> 5;
    const int warpM = wid & 3;          // 4 M quarters (32 rows each)
    const int warpN = wid >> 2;         // 2 N halves (32 cols each)
    const int g     = lane >> 2;
    const int tig   = lane & 3;

    const int NK = KRANGE / BK;         // 64

    for (;;) {
        if (tid == 0) s_tile = atomicAdd(&g_tile_ctr, 1);
        __syncthreads();
        const int s = s_tile;
        if (s >= NTILES) break;
        const int kz = s >> 7;          // 0..7
        const int mb = s & 127;         // 0..127

        const size_t rowBase = (size_t)mb * 128;
        const float* gA0 = adj + rowBase * N_NODES + (size_t)kz * KRANGE;
        const float* gH0 = g_h + (size_t)kz * KRANGE * OUT_F;

        float acc[2][4][4];
#pragma unroll
        for (int mt = 0; mt < 2; ++mt)
#pragma unroll
            for (int nt = 0; nt < 4; ++nt)
#pragma unroll
                for (int e = 0; e < 4; ++e) acc[mt][nt][e] = 0.f;

        auto issue = [&](int kt) {
            const int st = kt & (STAGES - 1);
            float4* As4 = smem + st * ST_F4;         // [128][8]  swizzled
            float4* Hs4 = As4 + A_ST_F4;             // [32][16]  swizzled
            const float* gA = gA0 + kt * BK;
#pragma unroll
            for (int i = 0; i < 4; ++i) {            // 128x32 = 1024 float4
                int e   = i * 256 + tid;
                int row = e >> 3;
                int c4  = e & 7;
                cp_async16(&As4[row * 8 + (c4 ^ (row & 7))],
                           gA + (size_t)row * N_NODES + c4 * 4);
            }
            const float* gH = gH0 + (size_t)kt * BK * OUT_F;
#pragma unroll
            for (int i = 0; i < 2; ++i) {            // 32x64 = 512 float4
                int e  = i * 256 + tid;
                int k  = e >> 4;
                int c4 = e & 15;
                cp_async16(&Hs4[k * 16 + (c4 ^ ((k & 3) << 1))],
                           gH + k * OUT_F + c4 * 4);
            }
        };

        issue(0); asm volatile("cp.async.commit_group;");
        issue(1); asm volatile("cp.async.commit_group;");
        issue(2); asm volatile("cp.async.commit_group;");

        for (int kt = 0; kt < NK; ++kt) {
            asm volatile("cp.async.wait_group 2;");
            __syncthreads();
            if (kt + 3 < NK) issue(kt + 3);
            asm volatile("cp.async.commit_group;");  // uniform group count

            const int st = kt & (STAGES - 1);
            const uint32_t* As = (const uint32_t*)(smem + st * ST_F4);
            const uint32_t* Hs = (const uint32_t*)(smem + st * ST_F4 + A_ST_F4);

#pragma unroll
            for (int ks = 0; ks < 4; ++ks) {
                const int k0 = ks * 8 + tig;
                const int k1 = k0 + 4;
                // A element (r,k) at word r*32 + (((k>>2)^(r&7))<<2) + (k&3)
                uint32_t afr[2][4];
#pragma unroll
                for (int mt = 0; mt < 2; ++mt) {
                    int r = warpM * 32 + mt * 16 + g;
                    afr[mt][0] = As[r * 32       + (((k0 >> 2) ^ (r & 7)) << 2) + (k0 & 3)];
                    afr[mt][1] = As[(r + 8) * 32 + (((k0 >> 2) ^ (r & 7)) << 2) + (k0 & 3)];
                    afr[mt][2] = As[r * 32       + (((k1 >> 2) ^ (r & 7)) << 2) + (k1 & 3)];
                    afr[mt][3] = As[(r + 8) * 32 + (((k1 >> 2) ^ (r & 7)) << 2) + (k1 & 3)];
                }
                // H element (k,n) at word k*64 + (n ^ ((k&3)<<3)); rna pre-rounded
                uint32_t bfr[4][2];
#pragma unroll
                for (int nt = 0; nt < 4; ++nt) {
                    int n = warpN * 32 + nt * 8 + g;
                    bfr[nt][0] = Hs[k0 * 64 + (n ^ ((k0 & 3) << 3))];
                    bfr[nt][1] = Hs[k1 * 64 + (n ^ ((k1 & 3) << 3))];
                }
#pragma unroll
                for (int mt = 0; mt < 2; ++mt)
#pragma unroll
                    for (int nt = 0; nt < 4; ++nt)
                        MMA_TF32(acc[mt][nt], afr[mt], bfr[nt]);
            }
        }

        // direct partial store for this tile
        float* part = g_part + (size_t)kz * N_NODES * OUT_F;
#pragma unroll
        for (int mt = 0; mt < 2; ++mt) {
            size_t r = rowBase + warpM * 32 + mt * 16 + g;
#pragma unroll
            for (int nt = 0; nt < 4; ++nt) {
                int c = warpN * 32 + nt * 8 + tig * 2;
                float2 v0, v1;
                v0.x = acc[mt][nt][0];
                v0.y = acc[mt][nt][1];
                v1.x = acc[mt][nt][2];
                v1.y = acc[mt][nt][3];
                *(float2*)&part[r * OUT_F + c]       = v0;
                *(float2*)&part[(r + 8) * OUT_F + c] = v1;
            }
        }
        __syncthreads();   // all threads done with smem before next tile fills
    }
}

// ---------------------------------------------------------------------------
// Kernel C: out = relu(sum_kz g_part[kz])
// ---------------------------------------------------------------------------
__global__ __launch_bounds__(256) void reduce_kernel(float* __restrict__ out)
{
    const int S = N_NODES * OUT_F / 4;     // 262144 float4
    int i = blockIdx.x * 256 + threadIdx.x;
    const float4* p = (const float4*)g_part;
    float4 v = p[i];
#pragma unroll
    for (int z = 1; z < KSPLIT; ++z) {
        float4 t = p[i + z * S];
        v.x += t.x; v.y += t.y; v.z += t.z; v.w += t.w;
    }
    v.x = fmaxf(v.x, 0.f);
    v.y = fmaxf(v.y, 0.f);
    v.z = fmaxf(v.z, 0.f);
    v.w = fmaxf(v.w, 0.f);
    ((float4*)out)[i] = v;
}

// ---------------------------------------------------------------------------
extern "C" void kernel_launch(void* const* d_in, const int* in_sizes, int n_in,
                              void* d_out, int out_size)
{
    const float* x   = (const float*)d_in[0];   // [16384, 256]
    const float* adj = (const float*)d_in[1];   // [16384, 16384]
    const float* W   = (const float*)d_in[2];   // [256, 64]
    const float* b   = (const float*)d_in[3];   // [64]
    float* out = (float*)d_out;                 // [16384, 64]

    cudaFuncSetAttribute(linear_kernel,
                         cudaFuncAttributeMaxDynamicSharedMemorySize, L_SMEM);
    cudaFuncSetAttribute(agg_kernel,
                         cudaFuncAttributeMaxDynamicSharedMemorySize, SMEM_BYTES);

    reset_kernel<<<1, 1>>>();
    linear_kernel<<<N_NODES / 64, 256, L_SMEM>>>(x, W, b);
    agg_kernel<<<PERSIST_CTAS, 256, SMEM_BYTES>>>(adj);
    reduce_kernel<<<N_NODES * OUT_F / 4 / 256, 256>>>(out);
}